// round 15
// baseline (speedup 1.0000x reference)
#include <cuda_runtime.h>
#include <cstdint>

#define L1D 4096
#define L2D 4096
#define NB 8
#define CC 3
#define TOT (NB * L2D)      // 32768 outputs per half
#define G 16
#define NC (G * G * G)      // 4096 cells
#define BIN_THREADS 1024
#define REFS_PER_T (L1D / BIN_THREADS)  // 4
#define SLANES 8                         // lanes cooperating per query
#define QPWARP (32 / SLANES)             // 4 queries per warp
#define S_THREADS 256                    // 8 warps per CTA
#define QCH ((S_THREADS / 32) * QPWARP)  // 32 queries per CTA
#define QSPLIT (L2D / QCH)               // 128

// Binned refs per batch: (x, y, z, oidx-bits) + cell starts.
__device__ float4         g_ref4[NB][L1D];
__device__ unsigned short g_cs[NB][NC + 1];

// Proven bit-exact XLA chain (rounds 8/10-14 passed, rel_err 0.0):
//   sr/sq = fl(fl(x*x + y*y) + z*z)     (mul/add, NO fma)
//   dot   = fma(qz,rz, fma(qy,ry, mul(qx,rx)))
//   d2    = fma(dot, -2, add(sq, sr))
static __device__ __forceinline__ float sumsq(float x, float y, float z) {
    return __fadd_rn(__fadd_rn(__fmul_rn(x, x), __fmul_rn(y, y)),
                     __fmul_rn(z, z));
}
static __device__ __forceinline__ float d2ref(float qx, float qy, float qz,
                                              float sq, float rx, float ry,
                                              float rz, float sr) {
    const float dot = __fmaf_rn(qz, rz, __fmaf_rn(qy, ry, __fmul_rn(qx, rx)));
    return __fmaf_rn(dot, -2.0f, __fadd_rn(sq, sr));
}
static __device__ __forceinline__ int cell_of(float x, float y, float z) {
    int cx = min(G - 1, max(0, (int)(x * (float)G)));
    int cy = min(G - 1, max(0, (int)(y * (float)G)));
    int cz = min(G - 1, max(0, (int)(z * (float)G)));
    return (cz * G + cy) * G + cx;
}

// Kernel 1: per-batch counting sort of refs into 16^3 cells (one CTA/batch).
__global__ __launch_bounds__(BIN_THREADS)
void nn_bin(const float* __restrict__ c1) {
    __shared__ unsigned int hist[NC];
    __shared__ unsigned int wsum[BIN_THREADS / 32];
    const int n = blockIdx.x;
    const int t = threadIdx.x;

    for (int i = t; i < NC; i += BIN_THREADS) hist[i] = 0;
    __syncthreads();

    float x[REFS_PER_T], y[REFS_PER_T], z[REFS_PER_T];
    int cell[REFS_PER_T];
#pragma unroll
    for (int k = 0; k < REFS_PER_T; k++) {
        const int l = k * BIN_THREADS + t;
        const float* p = c1 + (size_t)l * (NB * CC) + n * CC;
        x[k] = p[0]; y[k] = p[1]; z[k] = p[2];
        cell[k] = cell_of(x[k], y[k], z[k]);
        atomicAdd(&hist[cell[k]], 1u);
    }
    __syncthreads();

    // Exclusive prefix over 4096 counts: 4/thread -> warp scan -> warp sums.
    const int NPT = NC / BIN_THREADS;  // 4
    unsigned int loc[NPT], s = 0;
#pragma unroll
    for (int j = 0; j < NPT; j++) { loc[j] = hist[t * NPT + j]; s += loc[j]; }
    unsigned int v = s;
#pragma unroll
    for (int o = 1; o < 32; o <<= 1) {
        unsigned int u = __shfl_up_sync(0xffffffffu, v, o);
        if ((t & 31) >= o) v += u;
    }
    const unsigned int excl = v - s;
    if ((t & 31) == 31) wsum[t >> 5] = v;
    __syncthreads();
    if (t < BIN_THREADS / 32) {  // 32 warp sums -> one warp scans them
        unsigned int w = wsum[t], vv = w;
#pragma unroll
        for (int o = 1; o < 32; o <<= 1) {
            unsigned int u = __shfl_up_sync(0xffffffffu, vv, o);
            if (t >= o) vv += u;
        }
        wsum[t] = vv - w;
    }
    __syncthreads();
    unsigned int base = wsum[t >> 5] + excl;
#pragma unroll
    for (int j = 0; j < NPT; j++) {
        const unsigned int tmp = loc[j];
        hist[t * NPT + j] = base;                       // cursor for scatter
        g_cs[n][t * NPT + j] = (unsigned short)base;    // exclusive start
        base += tmp;
    }
    if (t == 0) g_cs[n][NC] = (unsigned short)L1D;
    __syncthreads();

    // Scatter refs; .w carries ORIGINAL index bits (sr recomputed later with
    // the identical sumsq => bit-identical d2 chain).
#pragma unroll
    for (int k = 0; k < REFS_PER_T; k++) {
        const int l = k * BIN_THREADS + t;
        const unsigned int pos = atomicAdd(&hist[cell[k]], 1u);
        g_ref4[n][pos] = make_float4(x[k], y[k], z[k], __uint_as_float((unsigned)l));
    }
}

// Evaluate one candidate against running (m, mi). Ties resolve to the
// smaller ORIGINAL index => first-occurrence argmin, scatter-order invariant.
static __device__ __forceinline__ void eval_cand(
    float4 rv, float qx, float qy, float qz, float sq, float& m, unsigned& mi) {
    const float sr = sumsq(rv.x, rv.y, rv.z);
    const float d = d2ref(qx, qy, qz, sq, rv.x, rv.y, rv.z, sr);
    const unsigned oi = __float_as_uint(rv.w);
    if (d < m) { m = d; mi = oi; }
    else if (d == m && oi < mi) { mi = oi; }
}

// Scan a contiguous ref range with next-iteration prefetch (hides L1 lat).
static __device__ __forceinline__ void scan_range(
    const float4* __restrict__ pR, unsigned s, unsigned e,
    float qx, float qy, float qz, float sq, float& m, unsigned& mi) {
    if (s >= e) return;
    float4 rv = pR[s];
    for (unsigned i = s + 1;; i++) {
        const bool more = i < e;
        float4 nx;
        if (more) nx = pR[i];          // prefetch before consuming rv
        eval_cand(rv, qx, qy, qz, sq, m, mi);
        if (!more) break;
        rv = nx;
    }
}

// Strided scan (step SLANES) used to split one row across the group.
static __device__ __forceinline__ void scan_strided(
    const float4* __restrict__ pR, unsigned s, unsigned e,
    float qx, float qy, float qz, float sq, float& m, unsigned& mi) {
    for (unsigned i = s; i < e; i += SLANES)
        eval_cand(pR[i], qx, qy, qz, sq, m, mi);
}

// 3-step reduce of (m, mi) across the 8-lane group.
static __device__ __forceinline__ void red8(unsigned gmask, float& m, unsigned& mi) {
#pragma unroll
    for (int o = SLANES / 2; o; o >>= 1) {
        const float om = __shfl_xor_sync(gmask, m, o);
        const unsigned omi = __shfl_xor_sync(gmask, mi, o);
        if (om < m || (om == m && omi < mi)) { m = om; mi = omi; }
    }
}

// Kernel 2: 8-LANE-PER-QUERY ring search over CONTIGUOUS X-ROWS.
// r=1: lane sub owns row sub (rows 0..7); row 8 stride-split across lanes.
// Zero SMEM; refs/starts via L1-cached LDG. Group control flow uniform.
__global__ __launch_bounds__(S_THREADS)
void nn_search(const float* __restrict__ c2, float* __restrict__ out) {
    const int qc = blockIdx.x;
    const int n  = blockIdx.y;
    const int t  = threadIdx.x;
    const int warp = t >> 5, lane = t & 31;
    const int g = lane >> 3, sub = lane & 7;
    const unsigned gmask = 0xFFu << (g * 8);
    const int ql  = warp * QPWARP + g;
    const int l2i = qc * QCH + ql;

    const float4* __restrict__ pR = &g_ref4[n][0];
    const unsigned short* __restrict__ pS = &g_cs[n][0];

    const float* p = c2 + (size_t)l2i * (NB * CC) + n * CC;  // 8-lane broadcast
    const float qx = p[0], qy = p[1], qz = p[2];
    const float sq = sumsq(qx, qy, qz);
    const int cx = min(G - 1, max(0, (int)(qx * (float)G)));
    const int cy = min(G - 1, max(0, (int)(qy * (float)G)));
    const int cz = min(G - 1, max(0, (int)(qz * (float)G)));

    float m = __int_as_float(0x7f800000);
    unsigned mi = 0xffffffffu;

    // ---- r = 1: rows 0..7 -> lane sub; row 8 (dz=+1,dy=+1) split ----
    {
        const int xlo = max(cx - 1, 0), xhi = min(cx + 1, G - 1);
        {
            const int dz = sub / 3 - 1, dy = sub % 3 - 1;   // rows 0..7
            const int z2 = cz + dz, y2 = cy + dy;
            if ((unsigned)z2 < G && (unsigned)y2 < G) {
                const int rowb = (z2 * G + y2) * G;
                const unsigned s = pS[rowb + xlo], e = pS[rowb + xhi + 1];
                scan_range(pR, s, e, qx, qy, qz, sq, m, mi);
            }
        }
        {
            const int z2 = cz + 1, y2 = cy + 1;             // row 8
            if ((unsigned)z2 < G && (unsigned)y2 < G) {
                const int rowb = (z2 * G + y2) * G;
                const unsigned s = pS[rowb + xlo], e = pS[rowb + xhi + 1];
                scan_strided(pR, s + sub, e, qx, qy, qz, sq, m, mi);
            }
        }
    }
    red8(gmask, m, mi);
    // Unexamined cells (Chebyshev > r) hold points with fl-d2 > (r*h)^2-1.2e-6;
    // margin 4e-6 => no bit-equal candidate outside the scanned region.
    const float h = 1.0f / (float)G;
    bool done = (m <= h * h * 0.999f - 4e-6f);

    if (!done) {
        // ---- r = 2: rescan full 5x5 rows x [cx-2..cx+2] (dups harmless) ----
        const int xlo = max(cx - 2, 0), xhi = min(cx + 2, G - 1);
#pragma unroll 4
        for (int j = sub; j < 25; j += SLANES) {
            const int dz = j / 5 - 2, dy = j % 5 - 2;
            const int z2 = cz + dz, y2 = cy + dy;
            if ((unsigned)z2 < G && (unsigned)y2 < G) {
                const int rowb = (z2 * G + y2) * G;
                const unsigned s = pS[rowb + xlo], e = pS[rowb + xhi + 1];
                scan_range(pR, s, e, qx, qy, qz, sq, m, mi);
            }
        }
        red8(gmask, m, mi);
        const float b2 = 2.0f * h;
        done = (m <= b2 * b2 * 0.999f - 4e-6f);

        if (!done) {  // exhaustive fallback (probability ~0, correctness only)
            scan_strided(pR, sub, L1D, qx, qy, qz, sq, m, mi);
            red8(gmask, m, mi);
        }
    }

    if (sub == 0) {
        const int o = l2i * NB + n;
        out[o] = (float)mi;        // cluster index (<= 4095, exact in fp32)
        out[TOT + o] = (float)n;   // batch index
    }
}

extern "C" void kernel_launch(void* const* d_in, const int* in_sizes, int n_in,
                              void* d_out, int out_size) {
    const float* c1 = (const float*)d_in[0];  // coords1 [L1, N, C]
    const float* c2 = (const float*)d_in[1];  // coords2 [L2, N, C]
    float* out = (float*)d_out;

    nn_bin<<<NB, BIN_THREADS>>>(c1);
    dim3 grid(QSPLIT, NB);
    nn_search<<<grid, S_THREADS>>>(c2, out);
}